// round 16
// baseline (speedup 1.0000x reference)
#include <cuda_runtime.h>
#include <cstdint>

#define NPIX 9216            // H*W = 96*96
#define BATCH 2
#define TOT (BATCH*NPIX)     // 18432
#define RPB 6                // rows per block: 3072 blocks = 6.92 waves of 444
#define RB 3                 // rows per merged batch (2 batches per block)
#define LOG2E 1.4426950408889634f

__device__ float g_p[TOT];   // p = sigmoid(x0-x1)

__device__ __forceinline__ float ex2(float x) {
    float r;
    asm("ex2.approx.ftz.f32 %0, %1;" : "=f"(r) : "f"(x));
    return r;
}
__device__ __forceinline__ float lg2(float x) {
    float r;
    asm("lg2.approx.ftz.f32 %0, %1;" : "=f"(r) : "f"(x));
    return r;
}

// Kernel 1: per-pixel prep (p only), wide grid, signals dependents ASAP.
__global__ void k_prep(const float* __restrict__ x) {
    int i = blockIdx.x * blockDim.x + threadIdx.x;   // quad index
    if (i < TOT / 4) {
        int b = (i * 4) / NPIX;
        int n4 = i - b * (NPIX / 4);
        const float4* x0 = reinterpret_cast<const float4*>(x + (size_t)(b * 2 + 0) * NPIX);
        const float4* x1 = reinterpret_cast<const float4*>(x + (size_t)(b * 2 + 1) * NPIX);
        float4 a = x0[n4], c = x1[n4];
        float4 p;
        p.x = 1.0f / (1.0f + __expf(c.x - a.x));
        p.y = 1.0f / (1.0f + __expf(c.y - a.y));
        p.z = 1.0f / (1.0f + __expf(c.z - a.z));
        p.w = 1.0f / (1.0f + __expf(c.w - a.w));
        reinterpret_cast<float4*>(g_p)[i] = p;
    }
    asm volatile("griddepcontrol.launch_dependents;" ::: "memory");
}

// Kernel 2: rows in batches of RB; 1 LDS feeds RB rows' exps; one barrier per
// batch (double-buffered reduction); k-outer store phase with RB independent
// STG.128 streams. attn[row,m] = 2^(a_r p_m - log2 S_r).
__global__ void __launch_bounds__(256, 3)
k_attn(const float* __restrict__ w, const float* __restrict__ cb,
       const float* __restrict__ gm,
       float* __restrict__ y, float* __restrict__ attn) {
    const int tid = threadIdx.x;
    const int lane = tid & 31, wid = tid >> 5;
    const int rowBase = blockIdx.x * RPB;      // 9216 % 6 == 0: no batch straddle
    const int b = rowBase / NPIX;

    __shared__ __align__(16) float sp[NPIX];   // 36 KB p tile
    __shared__ float sS[2][8 * RB], sT[2][8 * RB];   // double-buffered reductions

    asm volatile("griddepcontrol.wait;" ::: "memory");  // PDL: g_p ready

    {   // load p tile once per block (L2-resident source)
        const float4* __restrict__ src = reinterpret_cast<const float4*>(g_p + b * NPIX);
        float4* dst = reinterpret_cast<float4*>(sp);
#pragma unroll
        for (int k = 0; k < 9; k++)
            dst[tid + k * 256] = src[tid + k * 256];
    }
    __syncthreads();

    const float4* sp4 = reinterpret_cast<const float4*>(sp);

#pragma unroll 1
    for (int bt = 0; bt < RPB / RB; bt++) {
        const int row0 = rowBase + bt * RB;
        const int buf = bt & 1;

        float a2[RB];
#pragma unroll
        for (int r = 0; r < RB; r++)           // a = (2p-1)*log2e from the smem tile
            a2[r] = fmaf(2.0f * LOG2E, sp[row0 + r - b * NPIX], -LOG2E);

        // ---- compute phase: all RB rows per p element ----
        float S[RB], T[RB];
#pragma unroll
        for (int r = 0; r < RB; r++) { S[r] = 0.0f; T[r] = 0.0f; }
#pragma unroll
        for (int k = 0; k < 9; k++) {
            float4 pv = sp4[tid + k * 256];
#pragma unroll
            for (int r = 0; r < RB; r++) {
                float e0 = ex2(a2[r] * pv.x);
                float e1 = ex2(a2[r] * pv.y);
                float e2 = ex2(a2[r] * pv.z);
                float e3 = ex2(a2[r] * pv.w);
                S[r] += (e0 + e1) + (e2 + e3);
                T[r] = fmaf(pv.x, e0, T[r]); T[r] = fmaf(pv.y, e1, T[r]);
                T[r] = fmaf(pv.z, e2, T[r]); T[r] = fmaf(pv.w, e3, T[r]);
            }
        }

        // ---- block reduce RB x (S,T) ----
#pragma unroll
        for (int o = 16; o > 0; o >>= 1) {
#pragma unroll
            for (int r = 0; r < RB; r++) {
                S[r] += __shfl_xor_sync(0xFFFFFFFFu, S[r], o);
                T[r] += __shfl_xor_sync(0xFFFFFFFFu, T[r], o);
            }
        }
        if (lane == 0) {
#pragma unroll
            for (int r = 0; r < RB; r++) {
                sS[buf][wid * RB + r] = S[r];
                sT[buf][wid * RB + r] = T[r];
            }
        }
        __syncthreads();               // single barrier per batch (double-buffered)

        float c2[RB];
#pragma unroll
        for (int r = 0; r < RB; r++) {
            float St = 0.0f;
#pragma unroll
            for (int i = 0; i < 8; i++) St += sS[buf][i * RB + r];
            c2[r] = -lg2(St);          // fold 1/S into exponent
        }

        if (tid < RB) {                // fused conv1x1 + sigmoid epilogue (1 thread/row)
            const int r = tid;
            float St = 0.0f, Tt = 0.0f;
#pragma unroll
            for (int i = 0; i < 8; i++) { St += sS[buf][i * RB + r]; Tt += sT[buf][i * RB + r]; }
            float o0 = Tt / St;
            float p  = sp[row0 + r - b * NPIX];
            float g  = gm[0];
            float pre0 = fmaf(g, o0, p);
            float pre1 = fmaf(g, 1.0f - o0, 1.0f - p);
            float t = fmaf(w[0], pre0, fmaf(w[1], pre1, cb[0]));
            y[row0 + r] = 1.0f / (1.0f + __expf(-t));
        }

        // ---- store phase: k-outer, RB independent row streams ----
        float4* __restrict__ o0p = reinterpret_cast<float4*>(attn + (size_t)(row0 + 0) * NPIX);
        float4* __restrict__ o1p = reinterpret_cast<float4*>(attn + (size_t)(row0 + 1) * NPIX);
        float4* __restrict__ o2p = reinterpret_cast<float4*>(attn + (size_t)(row0 + 2) * NPIX);
        float4* outp[RB] = {o0p, o1p, o2p};
#pragma unroll
        for (int k = 0; k < 9; k++) {
            float4 pv = sp4[tid + k * 256];
            const int off = tid + k * 256;
#pragma unroll
            for (int r = 0; r < RB; r++) {
                float4 o;
                o.x = ex2(fmaf(a2[r], pv.x, c2[r]));
                o.y = ex2(fmaf(a2[r], pv.y, c2[r]));
                o.z = ex2(fmaf(a2[r], pv.z, c2[r]));
                o.w = ex2(fmaf(a2[r], pv.w, c2[r]));
                outp[r][off] = o;      // independent coalesced 128-bit streams
            }
        }
    }
}

extern "C" void kernel_launch(void* const* d_in, const int* in_sizes, int n_in,
                              void* d_out, int out_size) {
    const float* x  = (const float*)d_in[0];   // [2,2,96,96]
    const float* w  = (const float*)d_in[1];   // [2]
    const float* cb = (const float*)d_in[2];   // [1]
    const float* gm = (const float*)d_in[3];   // [1]
    float* out = (float*)d_out;                // [18432 y | 2*9216*9216 attn]
    float* yp = out;
    float* attn = out + TOT;

    k_prep<<<36, 128>>>(x);                    // 4608 threads, 1 float4 each

    // k_attn with Programmatic Dependent Launch (overlaps launch ramp w/ prep)
    cudaLaunchConfig_t cfg = {};
    cfg.gridDim  = dim3(TOT / RPB, 1, 1);
    cfg.blockDim = dim3(256, 1, 1);
    cfg.dynamicSmemBytes = 0;
    cfg.stream = 0;
    cudaLaunchAttribute attr[1];
    attr[0].id = cudaLaunchAttributeProgrammaticStreamSerialization;
    attr[0].val.programmaticStreamSerializationAllowed = 1;
    cfg.attrs = attr;
    cfg.numAttrs = 1;
    cudaLaunchKernelEx(&cfg, k_attn, w, cb, gm, yp, attn);
}

// round 17
// speedup vs baseline: 1.5477x; 1.5477x over previous
#include <cuda_runtime.h>
#include <cstdint>

#define NPIX 9216            // H*W = 96*96
#define BATCH 2
#define TOT (BATCH*NPIX)     // 18432
#define RPB 6                // rows per block: 3072 blocks = 6.92 waves of 444
#define RB 3                 // rows per merged batch (2 batches per block)

__device__ float g_p[TOT];   // p = sigmoid(x0-x1)
__device__ float g_a[TOT];   // a = (2p-1)*log2(e)

__device__ __forceinline__ float ex2(float x) {
    float r;
    asm("ex2.approx.ftz.f32 %0, %1;" : "=f"(r) : "f"(x));
    return r;
}
__device__ __forceinline__ float lg2(float x) {
    float r;
    asm("lg2.approx.ftz.f32 %0, %1;" : "=f"(r) : "f"(x));
    return r;
}

// Kernel 1: per-pixel prep (float4-vectorized), signals dependent launch early.
__global__ void k_prep(const float* __restrict__ x) {
    int i = blockIdx.x * blockDim.x + threadIdx.x;   // quad index
    if (i < TOT / 4) {
        int b = (i * 4) / NPIX;
        int n4 = i - b * (NPIX / 4);
        const float4* x0 = reinterpret_cast<const float4*>(x + (size_t)(b * 2 + 0) * NPIX);
        const float4* x1 = reinterpret_cast<const float4*>(x + (size_t)(b * 2 + 1) * NPIX);
        float4 a = x0[n4], c = x1[n4];
        float4 p, q;
        p.x = 1.0f / (1.0f + __expf(c.x - a.x));
        p.y = 1.0f / (1.0f + __expf(c.y - a.y));
        p.z = 1.0f / (1.0f + __expf(c.z - a.z));
        p.w = 1.0f / (1.0f + __expf(c.w - a.w));
        const float L2E = 1.4426950408889634f;
        q.x = (2.0f * p.x - 1.0f) * L2E;
        q.y = (2.0f * p.y - 1.0f) * L2E;
        q.z = (2.0f * p.z - 1.0f) * L2E;
        q.w = (2.0f * p.w - 1.0f) * L2E;
        reinterpret_cast<float4*>(g_p)[i] = p;
        reinterpret_cast<float4*>(g_a)[i] = q;
    }
    asm volatile("griddepcontrol.launch_dependents;" ::: "memory");
}

// Kernel 2: rows in batches of RB; 1 LDS feeds RB rows' exps; one barrier per
// batch (double-buffered reduction); k-outer store phase with RB independent
// STG.128 streams. attn[row,m] = 2^(a_r p_m - log2 S_r).
__global__ void __launch_bounds__(256, 3)
k_attn(const float* __restrict__ w, const float* __restrict__ cb,
       const float* __restrict__ gm,
       float* __restrict__ y, float* __restrict__ attn) {
    const int tid = threadIdx.x;
    const int lane = tid & 31, wid = tid >> 5;
    const int rowBase = blockIdx.x * RPB;      // 9216 % 6 == 0: no batch straddle
    const int b = rowBase / NPIX;

    __shared__ __align__(16) float sp[NPIX];   // 36 KB p tile
    __shared__ float sS[2][8 * RB], sT[2][8 * RB];   // double-buffered reductions

    asm volatile("griddepcontrol.wait;" ::: "memory");  // PDL: g_p/g_a ready

    {   // load p tile once per block (L2-resident source)
        const float4* __restrict__ src = reinterpret_cast<const float4*>(g_p + b * NPIX);
        float4* dst = reinterpret_cast<float4*>(sp);
#pragma unroll
        for (int k = 0; k < 9; k++)
            dst[tid + k * 256] = src[tid + k * 256];
    }
    __syncthreads();

    const float4* sp4 = reinterpret_cast<const float4*>(sp);

#pragma unroll 1
    for (int bt = 0; bt < RPB / RB; bt++) {
        const int row0 = rowBase + bt * RB;
        const int buf = bt & 1;

        float a2[RB];
#pragma unroll
        for (int r = 0; r < RB; r++) a2[r] = g_a[row0 + r];   // L2 hits

        // ---- compute phase: all RB rows per p element ----
        float S[RB], T[RB];
#pragma unroll
        for (int r = 0; r < RB; r++) { S[r] = 0.0f; T[r] = 0.0f; }
#pragma unroll
        for (int k = 0; k < 9; k++) {
            float4 pv = sp4[tid + k * 256];
#pragma unroll
            for (int r = 0; r < RB; r++) {
                float e0 = ex2(a2[r] * pv.x);
                float e1 = ex2(a2[r] * pv.y);
                float e2 = ex2(a2[r] * pv.z);
                float e3 = ex2(a2[r] * pv.w);
                S[r] += (e0 + e1) + (e2 + e3);
                T[r] = fmaf(pv.x, e0, T[r]); T[r] = fmaf(pv.y, e1, T[r]);
                T[r] = fmaf(pv.z, e2, T[r]); T[r] = fmaf(pv.w, e3, T[r]);
            }
        }

        // ---- block reduce RB x (S,T) ----
#pragma unroll
        for (int o = 16; o > 0; o >>= 1) {
#pragma unroll
            for (int r = 0; r < RB; r++) {
                S[r] += __shfl_xor_sync(0xFFFFFFFFu, S[r], o);
                T[r] += __shfl_xor_sync(0xFFFFFFFFu, T[r], o);
            }
        }
        if (lane == 0) {
#pragma unroll
            for (int r = 0; r < RB; r++) {
                sS[buf][wid * RB + r] = S[r];
                sT[buf][wid * RB + r] = T[r];
            }
        }
        __syncthreads();               // single barrier per batch (double-buffered)

        float c2[RB];
#pragma unroll
        for (int r = 0; r < RB; r++) {
            float St = 0.0f;
#pragma unroll
            for (int i = 0; i < 8; i++) St += sS[buf][i * RB + r];
            c2[r] = -lg2(St);          // fold 1/S into exponent
        }

        if (tid < RB) {                // fused conv1x1 + sigmoid epilogue (1 thread/row)
            const int r = tid;
            float St = 0.0f, Tt = 0.0f;
#pragma unroll
            for (int i = 0; i < 8; i++) { St += sS[buf][i * RB + r]; Tt += sT[buf][i * RB + r]; }
            float o0 = Tt / St;
            float p  = sp[row0 + r - b * NPIX];
            float g  = gm[0];
            float pre0 = fmaf(g, o0, p);
            float pre1 = fmaf(g, 1.0f - o0, 1.0f - p);
            float t = fmaf(w[0], pre0, fmaf(w[1], pre1, cb[0]));
            y[row0 + r] = 1.0f / (1.0f + __expf(-t));
        }

        // ---- store phase: k-outer, RB independent row streams ----
        float4* __restrict__ o0p = reinterpret_cast<float4*>(attn + (size_t)(row0 + 0) * NPIX);
        float4* __restrict__ o1p = reinterpret_cast<float4*>(attn + (size_t)(row0 + 1) * NPIX);
        float4* __restrict__ o2p = reinterpret_cast<float4*>(attn + (size_t)(row0 + 2) * NPIX);
        float4* outp[RB] = {o0p, o1p, o2p};
#pragma unroll
        for (int k = 0; k < 9; k++) {
            float4 pv = sp4[tid + k * 256];
            const int off = tid + k * 256;
#pragma unroll
            for (int r = 0; r < RB; r++) {
                float4 o;
                o.x = ex2(fmaf(a2[r], pv.x, c2[r]));
                o.y = ex2(fmaf(a2[r], pv.y, c2[r]));
                o.z = ex2(fmaf(a2[r], pv.z, c2[r]));
                o.w = ex2(fmaf(a2[r], pv.w, c2[r]));
                outp[r][off] = o;      // independent coalesced 128-bit streams
            }
        }
    }
}

extern "C" void kernel_launch(void* const* d_in, const int* in_sizes, int n_in,
                              void* d_out, int out_size) {
    const float* x  = (const float*)d_in[0];   // [2,2,96,96]
    const float* w  = (const float*)d_in[1];   // [2]
    const float* cb = (const float*)d_in[2];   // [1]
    const float* gm = (const float*)d_in[3];   // [1]
    float* out = (float*)d_out;                // [18432 y | 2*9216*9216 attn]
    float* yp = out;
    float* attn = out + TOT;

    k_prep<<<(TOT / 4 + 255) / 256, 256>>>(x);

    // k_attn with Programmatic Dependent Launch (overlaps launch ramp w/ prep)
    cudaLaunchConfig_t cfg = {};
    cfg.gridDim  = dim3(TOT / RPB, 1, 1);
    cfg.blockDim = dim3(256, 1, 1);
    cfg.dynamicSmemBytes = 0;
    cfg.stream = 0;
    cudaLaunchAttribute attr[1];
    attr[0].id = cudaLaunchAttributeProgrammaticStreamSerialization;
    attr[0].val.programmaticStreamSerializationAllowed = 1;
    cfg.attrs = attr;
    cfg.numAttrs = 1;
    cudaLaunchKernelEx(&cfg, k_attn, w, cb, gm, yp, attn);
}